// round 12
// baseline (speedup 1.0000x reference)
#include <cuda_runtime.h>
#include <cuda_fp16.h>

// Problem constants
#define BB 8
#define CC 4
#define DD 128
#define HH 128
#define WW 128
#define FDIM 512
#define VOL (1<<21)          // 128^3
#define NB 888               // persistent grid: 6 blocks/SM x 148 SMs (<= resident)
#define PREP_CHUNKS 2048u    // VOL/4/256 per batch
#define SAMP_CHUNKS 8192u    // VOL/256 per batch

// Per-batch affine coefficients: integer (w,h,d) -> (ix,iy,iz)
__device__ __align__(16) float g_A[BB * 12];

// Scratch (row-major x-pair): slot s = {c0..c3 @ x=s, c0..c3 @ x=s+1} = 16B.
__device__ uint4 g_scr[(size_t)BB * VOL];

// Global barrier state (sense-reversing via generation counter)
__device__ unsigned g_cnt = 0;
__device__ volatile unsigned g_gen = 0;

static __device__ __forceinline__ void grid_barrier() {
    __syncthreads();
    if (threadIdx.x == 0) {
        const unsigned gen = g_gen;
        __threadfence();                       // release my writes
        if (atomicAdd(&g_cnt, 1) == NB - 1) {
            g_cnt = 0;
            __threadfence();
            g_gen = gen + 1;                   // release
        } else {
            while (g_gen == gen) __nanosleep(64);
        }
        __threadfence();                       // acquire others' writes
    }
    __syncthreads();
}

static __device__ __forceinline__ unsigned pack2(float a, float b) {
    __half2 h = __floats2half2_rn(a, b);
    return *reinterpret_cast<unsigned*>(&h);
}

// Packed f32x2 ops (Blackwell)
#define MUL_F32X2(out, a, b) \
    asm("mul.rn.f32x2 %0, %1, %2;" : "=l"(out) : "l"(a), "l"(b))
#define FMA_F32X2(d, a, b, c) \
    asm("fma.rn.f32x2 %0, %1, %2, %3;" : "=l"(d) : "l"(a), "l"(b), "l"(c))
#define PACK_F32X2(out, lo, hi) \
    asm("mov.b64 %0, {%1, %2};" : "=l"(out) : "f"(lo), "f"(hi))
#define UNPACK_F32X2(lo, hi, in) \
    asm("mov.b64 {%0, %1}, %2;" : "=f"(lo), "=f"(hi) : "l"(in))

// ---------------------------------------------------------------------------
// prep chunk: 256 threads transpose 4096 voxels of batch b into the fp16
// x-pair scratch. Thread = 4 consecutive voxels; x+4 neighbor via shuffle.
// ---------------------------------------------------------------------------
static __device__ __forceinline__ void prep_chunk(const float* __restrict__ x,
                                                  int b, unsigned c) {
    const unsigned s = (c * 256 + threadIdx.x) << 2;   // first voxel, < VOL
    const float* base = x + ((size_t)b << 23);         // b*C*VOL

    float4 v0 = *(const float4*)(base + s);
    float4 v1 = *(const float4*)(base + VOL + s);
    float4 v2 = *(const float4*)(base + 2u * VOL + s);
    float4 v3 = *(const float4*)(base + 3u * VOL + s);

    float n0 = __shfl_down_sync(0xffffffffu, v0.x, 1);
    float n1 = __shfl_down_sync(0xffffffffu, v1.x, 1);
    float n2 = __shfl_down_sync(0xffffffffu, v2.x, 1);
    float n3 = __shfl_down_sync(0xffffffffu, v3.x, 1);
    if ((threadIdx.x & 31) == 31) {
        unsigned sn = s + 4; if (sn >= VOL) sn = VOL - 1;  // value unused (weight 0)
        n0 = base[sn];
        n1 = base[VOL + sn];
        n2 = base[2u * VOL + sn];
        n3 = base[3u * VOL + sn];
    }

    float a0[5] = {v0.x, v0.y, v0.z, v0.w, n0};
    float a1[5] = {v1.x, v1.y, v1.z, v1.w, n1};
    float a2[5] = {v2.x, v2.y, v2.z, v2.w, n2};
    float a3[5] = {v3.x, v3.y, v3.z, v3.w, n3};

    uint4* dst = g_scr + ((size_t)b << 21) + s;
    #pragma unroll
    for (int j = 0; j < 4; ++j) {
        uint4 slot;
        slot.x = pack2(a0[j],     a1[j]);
        slot.y = pack2(a2[j],     a3[j]);
        slot.z = pack2(a0[j + 1], a1[j + 1]);
        slot.w = pack2(a2[j + 1], a3[j + 1]);
        dst[j] = slot;
    }
}

// ---------------------------------------------------------------------------
// sample chunk: 256 threads sample 256 voxels of batch b (1 voxel/thread,
// 4 LDG.128 gathers, f32x2 packed lerps, warp-uniform interior fast path).
// ---------------------------------------------------------------------------
static __device__ __forceinline__ void sample_chunk(float* __restrict__ out,
        int b, unsigned c, float4 Ax, float4 Ay, float4 Az) {
    const unsigned tid = c * 256 + threadIdx.x;        // < VOL
    const int w = tid & (WW - 1);
    const int h = (tid >> 7) & (HH - 1);
    const int d = tid >> 14;
    const float fw = (float)w, fh = (float)h, fd = (float)d;

    const float ix = fmaf(Ax.x, fw, fmaf(Ax.y, fh, fmaf(Ax.z, fd, Ax.w)));
    const float iy =                fmaf(Ay.x, fh, fmaf(Ay.y, fd, Ay.z));
    const float iz = fmaf(Az.x, fw, fmaf(Az.y, fh, fmaf(Az.z, fd, Az.w)));

    const float fxf = floorf(ix), fyf = floorf(iy), fzf = floorf(iz);
    const int ix0 = (int)fxf, iy0 = (int)fyf, iz0 = (int)fzf;
    const float fx = ix - fxf, fy = iy - fyf, fz = iz - fzf;

    float wAv, wBv, wy0, wy1, wz0, wz1;
    int xs, y0c, y1c, z0c, z1c;

    const bool interior = (ix0 >= 0) & (ix0 < WW - 1) &
                          (iy0 >= 0) & (iy0 < HH - 1) &
                          (iz0 >= 0) & (iz0 < DD - 1);

    if (__all_sync(0xffffffffu, interior)) {
        wAv = 1.0f - fx; wBv = fx;
        wy0 = 1.0f - fy; wy1 = fy;
        wz0 = 1.0f - fz; wz1 = fz;
        xs = ix0; y0c = iy0; y1c = iy0 + 1; z0c = iz0; z1c = iz0 + 1;
    } else {
        const int x1 = ix0 + 1, y1 = iy0 + 1, z1 = iz0 + 1;
        const float wx0 = (ix0 >= 0 && ix0 < WW) ? (1.0f - fx) : 0.0f;
        const float wx1 = (x1  >= 0 && x1  < WW) ? fx          : 0.0f;
        wy0 = (iy0 >= 0 && iy0 < HH) ? (1.0f - fy) : 0.0f;
        wy1 = (y1  >= 0 && y1  < HH) ? fy          : 0.0f;
        wz0 = (iz0 >= 0 && iz0 < DD) ? (1.0f - fz) : 0.0f;
        wz1 = (z1  >= 0 && z1  < DD) ? fz          : 0.0f;
        xs  = min(max(ix0, 0), WW - 1);
        wAv = (ix0 >= 0) ? wx0 : wx1;   // weight for slot's first voxel
        wBv = (ix0 >= 0) ? wx1 : 0.0f;  // weight for slot's second voxel
        y0c = min(max(iy0, 0), HH - 1);
        y1c = min(max(y1,  0), HH - 1);
        z0c = min(max(iz0, 0), DD - 1);
        z1c = min(max(z1,  0), DD - 1);
    }

    const int zb0 = z0c << 14, zb1 = z1c << 14;
    const int yb0 = y0c << 7,  yb1 = y1c << 7;

    const uint4* p = g_scr + ((size_t)b << 21);

    const uint4 g00 = __ldg(p + (zb0 + yb0 + xs));
    const uint4 g01 = __ldg(p + (zb0 + yb1 + xs));
    const uint4 g10 = __ldg(p + (zb1 + yb0 + xs));
    const uint4 g11 = __ldg(p + (zb1 + yb1 + xs));

    const float c00 = wz0 * wy0;
    const float c01 = wz0 * wy1;
    const float c10 = wz1 * wy0;
    const float c11 = wz1 * wy1;

    unsigned long long WA, WB, acc01, acc23;
    PACK_F32X2(WA, wAv, wAv);
    PACK_F32X2(WB, wBv, wBv);
    {
        float zf = 0.0f;
        PACK_F32X2(acc01, zf, zf);
        acc23 = acc01;
    }

    #define COLUMN(g, cwf)                                                     \
    {                                                                          \
        float2 lo01 = __half22float2(*reinterpret_cast<const __half2*>(&g.x)); \
        float2 lo23 = __half22float2(*reinterpret_cast<const __half2*>(&g.y)); \
        float2 hi01 = __half22float2(*reinterpret_cast<const __half2*>(&g.z)); \
        float2 hi23 = __half22float2(*reinterpret_cast<const __half2*>(&g.w)); \
        unsigned long long L01, L23, H01, H23, CW, m0, m1, t01, t23;           \
        PACK_F32X2(L01, lo01.x, lo01.y);                                       \
        PACK_F32X2(L23, lo23.x, lo23.y);                                       \
        PACK_F32X2(H01, hi01.x, hi01.y);                                       \
        PACK_F32X2(H23, hi23.x, hi23.y);                                       \
        PACK_F32X2(CW, cwf, cwf);                                              \
        MUL_F32X2(m0, WB, H01);                                                \
        FMA_F32X2(t01, WA, L01, m0);                                           \
        MUL_F32X2(m1, WB, H23);                                                \
        FMA_F32X2(t23, WA, L23, m1);                                           \
        FMA_F32X2(acc01, CW, t01, acc01);                                      \
        FMA_F32X2(acc23, CW, t23, acc23);                                      \
    }

    COLUMN(g00, c00)
    COLUMN(g01, c01)
    COLUMN(g10, c10)
    COLUMN(g11, c11)

    float r0, r1, r2, r3;
    UNPACK_F32X2(r0, r1, acc01);
    UNPACK_F32X2(r2, r3, acc23);

    const unsigned base = ((unsigned)b << 23) + tid;   // b*C*VOL + tid
    out[base]              = r0;
    out[base + (1u << 21)] = r1;
    out[base + (2u << 21)] = r2;
    out[base + (3u << 21)] = r3;
}

// ---------------------------------------------------------------------------
// Fused persistent kernel: prep(0); bar; for b: [sample(b) 4:1 prep(b+1)]; bar.
// scratch(b) is only 33.5MB -> still L2-resident when sample(b) reads it.
// ---------------------------------------------------------------------------
__global__ void __launch_bounds__(256, 6)
fused_kernel(const float* __restrict__ x,
             const float* __restrict__ im_feat,
             const float* __restrict__ pos_w,
             const float* __restrict__ pos_b,
             float* __restrict__ out) {
    // Rotation GEMV + affine coefficients: block 0, warp per batch.
    if (blockIdx.x == 0) {
        const int wid = threadIdx.x >> 5;
        const int lane = threadIdx.x & 31;
        if (wid < BB) {
            float pm = 0.f, pr = 0.f;
            for (int j = lane; j < FDIM; j += 32) {
                float f = im_feat[wid * FDIM + j];
                pm = fmaf(f, pos_w[j], pm);
                pr = fmaf(f, pos_w[FDIM + j], pr);
            }
            #pragma unroll
            for (int s2 = 16; s2; s2 >>= 1) {
                pm += __shfl_xor_sync(0xffffffffu, pm, s2);
                pr += __shfl_xor_sync(0xffffffffu, pr, s2);
            }
            if (lane == 0) {
                float mu  = pm + pos_b[0];
                float rho = pr + pos_b[1];
                float cm = cosf(mu),  sm = sinf(mu);
                float cr = cosf(rho), sr = sinf(rho);
                const float SC = 128.0f / 127.0f;
                float* A = &g_A[wid * 12];
                float r0 = cm, r1 = sm * sr, r2 = -sm * cr;
                float r4 = cr, r5 = sr;
                float r6 = sm, r7 = -cm * sr, r8 = cm * cr;
                A[0] = r0 * SC;  A[1] = r1 * SC;  A[2] = r2 * SC;
                A[3] = 64.0f * (1.0f - (r0 + r1 + r2)) - 0.5f;
                A[4] = r4 * SC;  A[5] = r5 * SC;
                A[6] = 64.0f * (1.0f - (r4 + r5)) - 0.5f;
                A[7] = 0.0f;
                A[8] = r6 * SC;  A[9] = r7 * SC;  A[10] = r8 * SC;
                A[11] = 64.0f * (1.0f - (r6 + r7 + r8)) - 0.5f;
            }
        }
    }

    // Phase 0: prep batch 0
    for (unsigned c = blockIdx.x; c < PREP_CHUNKS; c += NB) prep_chunk(x, 0, c);
    grid_barrier();

    for (int b = 0; b < BB; ++b) {
        // Plain loads (written this launch by block 0; fenced by barrier).
        const float4 Ax = *(const float4*)&g_A[b * 12];
        const float4 Ay = *(const float4*)&g_A[b * 12 + 4];
        const float4 Az = *(const float4*)&g_A[b * 12 + 8];

        unsigned sc = blockIdx.x;
        unsigned pc = (b < BB - 1) ? blockIdx.x : PREP_CHUNKS;

        while (sc < SAMP_CHUNKS || pc < PREP_CHUNKS) {
            #pragma unroll 1
            for (int k = 0; k < 4 && sc < SAMP_CHUNKS; ++k) {
                sample_chunk(out, b, sc, Ax, Ay, Az);
                sc += NB;
            }
            if (pc < PREP_CHUNKS) {
                prep_chunk(x, b + 1, pc);
                pc += NB;
            }
        }

        if (b < BB - 1) grid_barrier();   // scratch(b+1) complete
    }
}

extern "C" void kernel_launch(void* const* d_in, const int* in_sizes, int n_in,
                              void* d_out, int out_size) {
    const float* x       = (const float*)d_in[0];
    const float* im_feat = (const float*)d_in[1];
    const float* pos_w   = (const float*)d_in[2];
    const float* pos_b   = (const float*)d_in[3];
    float* out = (float*)d_out;

    fused_kernel<<<NB, 256>>>(x, im_feat, pos_w, pos_b, out);
}

// round 13
// speedup vs baseline: 1.2097x; 1.2097x over previous
#include <cuda_runtime.h>
#include <cuda_fp16.h>

// Problem constants
#define BB 8
#define CC 4
#define DD 128
#define HH 128
#define WW 128
#define FDIM 512
#define VOL (1<<21)          // 128^3

// Per-batch affine coefficients: integer (w,h,d) -> (ix,iy,iz)
__device__ __align__(16) float g_A[BB * 12];

// Scratch, tiled layout: slot (xs,y,z) = {c0..c3 @ x=xs, c0..c3 @ x=xs+1} (16B).
// One 128B line = 8 slots = a 4x-by-2z tile:
//   index = (y<<14) + ((z>>1)<<8) + ((xs>>2)<<3) + ((z&1)<<2) + (xs&3)
__device__ uint4 g_scr[(size_t)BB * VOL];

static __device__ __forceinline__ unsigned pack2(float a, float b) {
    __half2 h = __floats2half2_rn(a, b);
    return *reinterpret_cast<unsigned*>(&h);
}

// Packed f32x2 ops (Blackwell)
#define MUL_F32X2(out, a, b) \
    asm("mul.rn.f32x2 %0, %1, %2;" : "=l"(out) : "l"(a), "l"(b))
#define FMA_F32X2(d, a, b, c) \
    asm("fma.rn.f32x2 %0, %1, %2, %3;" : "=l"(d) : "l"(a), "l"(b), "l"(c))
#define PACK_F32X2(out, lo, hi) \
    asm("mov.b64 %0, {%1, %2};" : "=l"(out) : "f"(lo), "f"(hi))
#define UNPACK_F32X2(lo, hi, in) \
    asm("mov.b64 {%0, %1}, %2;" : "=f"(lo), "=f"(hi) : "l"(in))

// ---------------------------------------------------------------------------
// Kernel 1: prep with smem-staged tiled writes.
// Block = 1024 voxels: 4 y-rows x 2 z-planes x 128 x, for one batch.
//   Load : per thread one float4/channel from row (y,z)  -> 512B coalesced.
//   Stage: slots packed into 16KB smem at tiled in-line position, XOR swizzle.
//   Flush: coalesced STG.128, lanes at 16B stride (4 lines/instr).
// Block 0 additionally computes the per-batch affine coefficients.
// grid = BB * 2048 blocks, 256 threads.
// ---------------------------------------------------------------------------
__global__ void __launch_bounds__(256)
prep_kernel(const float* __restrict__ x,
            const float* __restrict__ im_feat,
            const float* __restrict__ pos_w,
            const float* __restrict__ pos_b) {
    __shared__ uint4 sm[128 * 8];   // 128 lines x 8 slots = 16KB

    if (blockIdx.x == 0) {
        const int wid = threadIdx.x >> 5;
        const int lane = threadIdx.x & 31;
        if (wid < BB) {
            float pm = 0.f, pr = 0.f;
            for (int j = lane; j < FDIM; j += 32) {
                float f = im_feat[wid * FDIM + j];
                pm = fmaf(f, pos_w[j], pm);
                pr = fmaf(f, pos_w[FDIM + j], pr);
            }
            #pragma unroll
            for (int s2 = 16; s2; s2 >>= 1) {
                pm += __shfl_xor_sync(0xffffffffu, pm, s2);
                pr += __shfl_xor_sync(0xffffffffu, pr, s2);
            }
            if (lane == 0) {
                float mu  = pm + pos_b[0];
                float rho = pr + pos_b[1];
                float cm = cosf(mu),  sm2 = sinf(mu);
                float cr = cosf(rho), sr = sinf(rho);
                const float SC = 128.0f / 127.0f;
                float* A = &g_A[wid * 12];
                float r0 = cm, r1 = sm2 * sr, r2 = -sm2 * cr;
                float r4 = cr, r5 = sr;
                float r6 = sm2, r7 = -cm * sr, r8 = cm * cr;
                A[0] = r0 * SC;  A[1] = r1 * SC;  A[2] = r2 * SC;
                A[3] = 64.0f * (1.0f - (r0 + r1 + r2)) - 0.5f;
                A[4] = r4 * SC;  A[5] = r5 * SC;
                A[6] = 64.0f * (1.0f - (r4 + r5)) - 0.5f;
                A[7] = 0.0f;
                A[8] = r6 * SC;  A[9] = r7 * SC;  A[10] = r8 * SC;
                A[11] = 64.0f * (1.0f - (r6 + r7 + r8)) - 0.5f;
            }
        }
    }

    const unsigned blk = blockIdx.x;
    const unsigned b   = blk >> 11;          // batch
    const unsigned rem = blk & 2047u;
    const unsigned zt  = rem >> 5;           // 0..63  (z-pair)
    const unsigned yq  = rem & 31u;          // 0..31  (y-quad)

    const unsigned t  = threadIdx.x;
    const unsigned xq = t & 31u;             // lane = x-quad (0..31)
    const unsigned r  = t >> 5;              // warp = row id (0..7)
    const unsigned dz = r >> 2;              // 0..1
    const unsigned dy = r & 3u;              // 0..3
    const unsigned y  = (yq << 2) + dy;
    const unsigned z  = (zt << 1) + dz;

    const float* base = x + ((size_t)b << 23);          // b*C*VOL
    const unsigned s = (z << 14) + (y << 7) + (xq << 2);

    float4 v0 = *(const float4*)(base + s);
    float4 v1 = *(const float4*)(base + VOL + s);
    float4 v2 = *(const float4*)(base + 2u * VOL + s);
    float4 v3 = *(const float4*)(base + 3u * VOL + s);

    // x+4 neighbor from next lane; lane 31 duplicates x=127 (slot xs=127's
    // second half is only ever read with weight 0).
    float n0 = __shfl_down_sync(0xffffffffu, v0.x, 1);
    float n1 = __shfl_down_sync(0xffffffffu, v1.x, 1);
    float n2 = __shfl_down_sync(0xffffffffu, v2.x, 1);
    float n3 = __shfl_down_sync(0xffffffffu, v3.x, 1);
    if (xq == 31) { n0 = v0.w; n1 = v1.w; n2 = v2.w; n3 = v3.w; }

    float a0[5] = {v0.x, v0.y, v0.z, v0.w, n0};
    float a1[5] = {v1.x, v1.y, v1.z, v1.w, n1};
    float a2[5] = {v2.x, v2.y, v2.z, v2.w, n2};
    float a3[5] = {v3.x, v3.y, v3.z, v3.w, n3};

    // Stage slots: line L = dy*32 + xq; pos = dz*4 + k; swizzle pos by L&7.
    const unsigned L = (dy << 5) + xq;
    const unsigned rot8 = L & 7u;
    #pragma unroll
    for (unsigned k = 0; k < 4; ++k) {
        uint4 slot;
        slot.x = pack2(a0[k],     a1[k]);
        slot.y = pack2(a2[k],     a3[k]);
        slot.z = pack2(a0[k + 1], a1[k + 1]);
        slot.w = pack2(a2[k + 1], a3[k + 1]);
        sm[(L << 3) + (((dz << 2) + k) ^ rot8)] = slot;
    }
    __syncthreads();

    // Coalesced flush: thread t -> y-group dy_s = t>>6, i = t&63.
    // Iter k writes global uint4 q = k*64 + i within the group (lanes 16B apart).
    const unsigned dy_s = t >> 6;
    const unsigned i    = t & 63u;
    uint4* gdst = g_scr + ((size_t)b << 21)
                + (((size_t)((yq << 2) + dy_s)) << 14) + (zt << 8);
    #pragma unroll
    for (unsigned k = 0; k < 4; ++k) {
        const unsigned q  = (k << 6) + i;              // 0..255
        const unsigned Lg = (dy_s << 5) + (q >> 3);    // smem line
        const unsigned pos = q & 7u;
        gdst[q] = sm[(Lg << 3) + (pos ^ (Lg & 7u))];
    }
}

// ---------------------------------------------------------------------------
// Kernel 2: rotated trilinear grid_sample (R9 body — measured 119.7us, L1 94%).
// 1 voxel/thread, 4 LDG.128 from the tiled scratch, f32x2 packed lerps.
// grid = (VOL/256, B), block 256.
// ---------------------------------------------------------------------------
__global__ void __launch_bounds__(256, 8)
sample_kernel(float* __restrict__ out) {
    const int b = blockIdx.y;

    const float4 Ax = __ldg((const float4*)&g_A[b * 12]);
    const float4 Ay = __ldg((const float4*)&g_A[b * 12 + 4]);
    const float4 Az = __ldg((const float4*)&g_A[b * 12 + 8]);

    const unsigned tid = blockIdx.x * 256 + threadIdx.x;   // < VOL
    const int w = tid & (WW - 1);
    const int h = (tid >> 7) & (HH - 1);
    const int d = tid >> 14;
    const float fw = (float)w, fh = (float)h, fd = (float)d;

    const float ix = fmaf(Ax.x, fw, fmaf(Ax.y, fh, fmaf(Ax.z, fd, Ax.w)));
    const float iy =                fmaf(Ay.x, fh, fmaf(Ay.y, fd, Ay.z));
    const float iz = fmaf(Az.x, fw, fmaf(Az.y, fh, fmaf(Az.z, fd, Az.w)));

    const float fxf = floorf(ix), fyf = floorf(iy), fzf = floorf(iz);
    const int ix0 = (int)fxf, iy0 = (int)fyf, iz0 = (int)fzf;
    const float fx = ix - fxf, fy = iy - fyf, fz = iz - fzf;

    float wAv, wBv, wy0, wy1, wz0, wz1;
    int xs, y0c, y1c, z0c, z1c;

    const bool interior = (ix0 >= 0) & (ix0 < WW - 1) &
                          (iy0 >= 0) & (iy0 < HH - 1) &
                          (iz0 >= 0) & (iz0 < DD - 1);

    if (__all_sync(0xffffffffu, interior)) {
        wAv = 1.0f - fx; wBv = fx;
        wy0 = 1.0f - fy; wy1 = fy;
        wz0 = 1.0f - fz; wz1 = fz;
        xs = ix0; y0c = iy0; y1c = iy0 + 1; z0c = iz0; z1c = iz0 + 1;
    } else {
        const int x1 = ix0 + 1, y1 = iy0 + 1, z1 = iz0 + 1;
        const float wx0 = (ix0 >= 0 && ix0 < WW) ? (1.0f - fx) : 0.0f;
        const float wx1 = (x1  >= 0 && x1  < WW) ? fx          : 0.0f;
        wy0 = (iy0 >= 0 && iy0 < HH) ? (1.0f - fy) : 0.0f;
        wy1 = (y1  >= 0 && y1  < HH) ? fy          : 0.0f;
        wz0 = (iz0 >= 0 && iz0 < DD) ? (1.0f - fz) : 0.0f;
        wz1 = (z1  >= 0 && z1  < DD) ? fz          : 0.0f;
        xs  = min(max(ix0, 0), WW - 1);
        wAv = (ix0 >= 0) ? wx0 : wx1;   // weight for slot's first voxel
        wBv = (ix0 >= 0) ? wx1 : 0.0f;  // weight for slot's second voxel
        y0c = min(max(iy0, 0), HH - 1);
        y1c = min(max(y1,  0), HH - 1);
        z0c = min(max(iz0, 0), DD - 1);
        z1c = min(max(z1,  0), DD - 1);
    }

    // Tiled offsets
    const int xpart = ((xs >> 2) << 3) + (xs & 3);
    const int zp0 = ((z0c >> 1) << 8) + ((z0c & 1) << 2);
    const int zp1 = ((z1c >> 1) << 8) + ((z1c & 1) << 2);
    const int yp0 = y0c << 14, yp1 = y1c << 14;

    const uint4* p = g_scr + ((size_t)b << 21);

    const uint4 g00 = __ldg(p + (yp0 + zp0 + xpart));   // (y0, z0)
    const uint4 g01 = __ldg(p + (yp1 + zp0 + xpart));   // (y1, z0)
    const uint4 g10 = __ldg(p + (yp0 + zp1 + xpart));   // (y0, z1)
    const uint4 g11 = __ldg(p + (yp1 + zp1 + xpart));   // (y1, z1)

    const float c00 = wz0 * wy0;
    const float c01 = wz0 * wy1;
    const float c10 = wz1 * wy0;
    const float c11 = wz1 * wy1;

    unsigned long long WA, WB, acc01, acc23;
    PACK_F32X2(WA, wAv, wAv);
    PACK_F32X2(WB, wBv, wBv);
    {
        float zf = 0.0f;
        PACK_F32X2(acc01, zf, zf);
        acc23 = acc01;
    }

    #define COLUMN(g, cwf)                                                     \
    {                                                                          \
        float2 lo01 = __half22float2(*reinterpret_cast<const __half2*>(&g.x)); \
        float2 lo23 = __half22float2(*reinterpret_cast<const __half2*>(&g.y)); \
        float2 hi01 = __half22float2(*reinterpret_cast<const __half2*>(&g.z)); \
        float2 hi23 = __half22float2(*reinterpret_cast<const __half2*>(&g.w)); \
        unsigned long long L01, L23, H01, H23, CW, m0, m1, t01, t23;           \
        PACK_F32X2(L01, lo01.x, lo01.y);                                       \
        PACK_F32X2(L23, lo23.x, lo23.y);                                       \
        PACK_F32X2(H01, hi01.x, hi01.y);                                       \
        PACK_F32X2(H23, hi23.x, hi23.y);                                       \
        PACK_F32X2(CW, cwf, cwf);                                              \
        MUL_F32X2(m0, WB, H01);                                                \
        FMA_F32X2(t01, WA, L01, m0);                                           \
        MUL_F32X2(m1, WB, H23);                                                \
        FMA_F32X2(t23, WA, L23, m1);                                           \
        FMA_F32X2(acc01, CW, t01, acc01);                                      \
        FMA_F32X2(acc23, CW, t23, acc23);                                      \
    }

    COLUMN(g00, c00)
    COLUMN(g01, c01)
    COLUMN(g10, c10)
    COLUMN(g11, c11)

    float r0, r1, r2, r3;
    UNPACK_F32X2(r0, r1, acc01);
    UNPACK_F32X2(r2, r3, acc23);

    const unsigned base = ((unsigned)b << 23) + tid;   // b*C*VOL + tid
    out[base]              = r0;
    out[base + (1u << 21)] = r1;
    out[base + (2u << 21)] = r2;
    out[base + (3u << 21)] = r3;
}

extern "C" void kernel_launch(void* const* d_in, const int* in_sizes, int n_in,
                              void* d_out, int out_size) {
    const float* x       = (const float*)d_in[0];
    const float* im_feat = (const float*)d_in[1];
    const float* pos_w   = (const float*)d_in[2];
    const float* pos_b   = (const float*)d_in[3];
    float* out = (float*)d_out;

    prep_kernel<<<BB * 2048, 256>>>(x, im_feat, pos_w, pos_b);
    dim3 grid(VOL / 256, BB);
    sample_kernel<<<grid, 256>>>(out);
}